// round 7
// baseline (speedup 1.0000x reference)
#include <cuda_runtime.h>

// x[64, 64, 64, 128] fp32.
//   out1 = FWHT over axis 1 (i, len 64); out2 = FWHT over axis 2 (j) of out1.
// d_out = [out1 | out2].
//
// Fused single pass (384 MB total traffic vs 512 MB for two-pass):
//  - CTA owns one batch b and an 8-channel chunk (32B = full DRAM sector).
//  - Phase A: each thread owns an i-column (fixed j,c): loads x directly
//    from gmem (4x32B sectors per warp op), FWHT_i in registers, stores out1
//    straight from registers (same granule), and deposits into the smem
//    plane for the transpose.
//  - Phase B: each thread owns a j-row (fixed i,c): reads smem, FWHT_j in
//    registers, writes back to smem.
//  - Final: coalesced float4 store of out2 from smem.
//  Only 2 barriers; STG queues drain asynchronously across phases/CTAs.

#define THREADS 512
#define ROWF 520          // 64*8 + 8 pad; conflict-free for column & row patterns
#define SMEM_BYTES (64 * ROWF * 4)   // 133,120 B -> 1 CTA/SM

__global__ __launch_bounds__(THREADS, 1)
void wht2_fused(const float* __restrict__ x,
                float* __restrict__ out1,
                float* __restrict__ out2)
{
    extern __shared__ float sm[];

    const int t  = threadIdx.x;
    const int b  = blockIdx.x >> 4;           // 64 batches
    const int cc = blockIdx.x & 15;           // 16 chunks of 8 channels
    const size_t base = (size_t)b * (64 * 64 * 128) + cc * 8;

    float v[64];

    // ---------------- phase A: FWHT over i ----------------
    {
        const int j = t >> 3;                 // 0..63
        const int c = t & 7;                  // 0..7
        const float* px = x + base + j * 128 + c;
#pragma unroll
        for (int i = 0; i < 64; i++)
            v[i] = __ldcs(px + (size_t)i * 8192);

#pragma unroll
        for (int h = 1; h < 64; h <<= 1)
#pragma unroll
            for (int s = 0; s < 64; s += 2 * h)
#pragma unroll
                for (int k = 0; k < h; k++) {
                    float a = v[s + k], bb = v[s + k + h];
                    v[s + k]     = a + bb;
                    v[s + k + h] = a - bb;
                }

        float* po1 = out1 + base + j * 128 + c;
#pragma unroll
        for (int i = 0; i < 64; i++) {
            __stcs(po1 + (size_t)i * 8192, v[i]);   // 32B-granule warp stores
            sm[i * ROWF + t] = v[i];                // conflict-free STS
        }
    }
    __syncthreads();

    // ---------------- phase B: FWHT over j ----------------
    {
        const int i = t >> 3;                 // 0..63
        const int c = t & 7;
        const int row = i * ROWF + c;
#pragma unroll
        for (int j = 0; j < 64; j++)
            v[j] = sm[row + j * 8];

#pragma unroll
        for (int h = 1; h < 64; h <<= 1)
#pragma unroll
            for (int s = 0; s < 64; s += 2 * h)
#pragma unroll
                for (int k = 0; k < h; k++) {
                    float a = v[s + k], bb = v[s + k + h];
                    v[s + k]     = a + bb;
                    v[s + k + h] = a - bb;
                }

#pragma unroll
        for (int j = 0; j < 64; j++)
            sm[row + j * 8] = v[j];
    }
    __syncthreads();

    // ---------------- store out2: smem -> gmem, float4 ----------------
#pragma unroll
    for (int r = 0; r < 16; r++) {
        int lin  = r * THREADS + t;           // 0..8191 over (i, j, half)
        int half = lin & 1;
        int j    = (lin >> 1) & 63;
        int i    = lin >> 7;
        float4 val = *reinterpret_cast<float4*>(sm + i * ROWF + j * 8 + half * 4);
        float* p = out2 + base + (size_t)i * 8192 + j * 128 + half * 4;
        __stcs(reinterpret_cast<float4*>(p), val);
    }
}

extern "C" void kernel_launch(void* const* d_in, const int* in_sizes, int n_in,
                              void* d_out, int out_size)
{
    const float* x = (const float*)d_in[0];
    float* out1 = (float*)d_out;
    float* out2 = out1 + (size_t)64 * 64 * 64 * 128;

    cudaFuncSetAttribute(wht2_fused,
                         cudaFuncAttributeMaxDynamicSharedMemorySize, SMEM_BYTES);

    wht2_fused<<<64 * 16, THREADS, SMEM_BYTES>>>(x, out1, out2);
}

// round 8
// speedup vs baseline: 1.3171x; 1.3171x over previous
#include <cuda_runtime.h>

// x[64, 64, 64, 128] fp32.
//   out1 = FWHT along axis 1 (i), stride 8192 floats
//   out2 = FWHT along axis 2 (j) of out1, stride 128 floats
// d_out = [out1 | out2].
//
// Software-pipelined single kernel: work is split into 8 chunks of 8 batches.
// Pass-1 blocks (FWHT_i: x -> out1) and pass-2 blocks (FWHT_j: out1 -> out2)
// for the same chunk are ordered so pass 2 runs right after pass 1 finishes
// that chunk -> the 16 MB out1 slice is still dirty-resident in L2 (126 MB),
// so pass-2 reads are L2 hits and out1 costs DRAM only once (writeback).
// Effective DRAM traffic ~384 MB instead of 512 MB.
// Per-chunk completion counters (zeroed by a prologue kernel each call) give
// the cross-pass dependency; block ordering guarantees spinning consumers
// always coexist with runnable producers (no deadlock).

#define THREADS 256
#define NB 64
#define CHUNK_B 8
#define NCHUNK (NB / CHUNK_B)                    // 8
#define COLS_PER_B 8192u                          // 64 j * 128 c (= 64 i * 128 c)
#define BPC ((int)(CHUNK_B * COLS_PER_B / THREADS))  // 256 blocks per chunk-pass
#define GRID (2 * NCHUNK * BPC)                   // 4096

__device__ int g_cnt[NCHUNK];

__global__ void reset_counters()
{
    if (threadIdx.x < NCHUNK) g_cnt[threadIdx.x] = 0;
}

__device__ __forceinline__ void butterfly64(float v[64])
{
#pragma unroll
    for (int h = 1; h < 64; h <<= 1)
#pragma unroll
        for (int s = 0; s < 64; s += 2 * h)
#pragma unroll
            for (int k = 0; k < h; k++) {
                float a = v[s + k], b = v[s + k + h];
                v[s + k]     = a + b;
                v[s + k + h] = a - b;
            }
}

__global__ __launch_bounds__(THREADS)
void wht2_pipe(const float* __restrict__ x,
               float* __restrict__ out1,
               float* __restrict__ out2)
{
    // ---- decode (pass, chunk, sub) from blockIdx with pipelined ordering ----
    // layout: [k1c0][k1c1][k2c0][k1c2][k2c1]...[k1c7][k2c6][k2c7]
    const int bid = blockIdx.x;
    int pass, chunk, sub;
    if (bid < 2 * BPC) {
        pass = 0; chunk = bid / BPC; sub = bid % BPC;
    } else {
        int g = (bid - 2 * BPC) / (2 * BPC);
        int r = (bid - 2 * BPC) % (2 * BPC);
        if (g < NCHUNK - 2) {
            if (r < BPC) { pass = 1; chunk = g;     sub = r; }
            else         { pass = 0; chunk = g + 2; sub = r - BPC; }
        } else {
            pass = 1; chunk = (r < BPC) ? (NCHUNK - 2) : (NCHUNK - 1); sub = r % BPC;
        }
    }

    const unsigned col = (unsigned)chunk * (CHUNK_B * COLS_PER_B)
                       + (unsigned)sub * THREADS + threadIdx.x;

    float v[64];

    if (pass == 0) {
        // ---------------- pass 1: out1 = FWHT_i(x), stride 8192 ----------------
        const size_t base = (size_t)(col / 8192u) * (64u * 8192u) + (col % 8192u);
        const float* px = x + base;
#pragma unroll
        for (int k = 0; k < 64; k++)
            v[k] = __ldcs(px + (size_t)k * 8192);      // use-once read of x

        butterfly64(v);

        float* po = out1 + base;
#pragma unroll
        for (int k = 0; k < 64; k++)
            po[(size_t)k * 8192] = v[k];               // default: keep in L2

        __threadfence();                                // stores visible GPU-wide
        __syncthreads();
        if (threadIdx.x == 0)
            atomicAdd(&g_cnt[chunk], 1);
    } else {
        // ---------------- pass 2: out2 = FWHT_j(out1), stride 128 ----------------
        if (threadIdx.x == 0) {
            while (*(volatile int*)&g_cnt[chunk] < BPC)
                __nanosleep(64);
        }
        __syncthreads();
        __threadfence();                                // acquire side

        const size_t base = (size_t)(col / 128u) * (64u * 128u) + (col % 128u);
        const float* pi = out1 + base;
#pragma unroll
        for (int k = 0; k < 64; k++)
            v[k] = __ldcs(pi + (size_t)k * 128);       // L2-hot, evict after read

        butterfly64(v);

        float* po = out2 + base;
#pragma unroll
        for (int k = 0; k < 64; k++)
            __stcs(po + (size_t)k * 128, v[k]);        // use-once write
    }
}

extern "C" void kernel_launch(void* const* d_in, const int* in_sizes, int n_in,
                              void* d_out, int out_size)
{
    const float* x = (const float*)d_in[0];
    float* out1 = (float*)d_out;
    float* out2 = out1 + (size_t)64 * 64 * 64 * 128;

    reset_counters<<<1, 32>>>();
    wht2_pipe<<<GRID, THREADS>>>(x, out1, out2);
}